// round 8
// baseline (speedup 1.0000x reference)
#include <cuda_runtime.h>
#include <math.h>

#define Bsz  4096
#define Tt   512
#define INP  25
#define Hh   50
#define Gg   200
#define KTOT 75
#define KSPL 38          // kh0: k in [0,38), kh1: [38,75)
#define ROWS 28
#define NTH  704         // 22 warps
#define GRID 147

typedef unsigned long long u64;

__device__ __forceinline__ float sigf(float v) {
    return __fdividef(1.0f, 1.0f + __expf(-v));
}
__device__ __forceinline__ float tanh_fast(float v) {
    return fmaf(2.0f, __fdividef(1.0f, 1.0f + __expf(-2.0f * v)), -1.0f);
}
__device__ __forceinline__ u64 pack2(float lo, float hi) {
    u64 d; asm("mov.b64 %0, {%1, %2};" : "=l"(d) : "f"(lo), "f"(hi)); return d;
}
__device__ __forceinline__ void unpack2(u64 d, float& lo, float& hi) {
    asm("mov.b64 {%0, %1}, %2;" : "=f"(lo), "=f"(hi) : "l"(d));
}
__device__ __forceinline__ u64 fma2(u64 a, u64 b, u64 c) {
    u64 d; asm("fma.rn.f32x2 %0, %1, %2, %3;" : "=l"(d) : "l"(a), "l"(b), "l"(c)); return d;
}
__device__ __forceinline__ u64 add2(u64 a, u64 b) {
    u64 d; asm("add.rn.f32x2 %0, %1, %2;" : "=l"(d) : "l"(a), "l"(b)); return d;
}
// exchange a u64 with the pair lane (xor 1): 2 shfl.32, no repack of the kept value
__device__ __forceinline__ u64 shfl_pair64(u64 v) {
    float lo, hi; unpack2(v, lo, hi);
    lo = __shfl_xor_sync(0xffffffffu, lo, 1);
    hi = __shfl_xor_sync(0xffffffffu, hi, 1);
    return pack2(lo, hi);
}

__global__ void __launch_bounds__(NTH, 1)
bayes_lstm_kernel(const float* __restrict__ x,
                  const float* __restrict__ wi_mu, const float* __restrict__ wi_rho,
                  const float* __restrict__ wh_mu, const float* __restrict__ wh_rho,
                  const float* __restrict__ b_mu,  const float* __restrict__ b_rho,
                  const float* __restrict__ lin_w, const float* __restrict__ lin_b,
                  const float* __restrict__ eps_wi, const float* __restrict__ eps_wh,
                  const float* __restrict__ eps_b,
                  float* __restrict__ out)
{
    extern __shared__ float sm[];
    float* w_s = sm;                     // [75][Gg] gate-interleaved: w_s[k][jj*4+g] = W[k][g*50+jj]
    float* xhA = w_s + KTOT * Gg;        // [75][ROWS] buf 0 (x rows 0..24, h rows 25..74)
    float* xhB = xhA + KTOT * ROWS;      // [75][ROWS] buf 1

    const int tid  = threadIdx.x;
    const long row0 = (long)blockIdx.x * ROWS;

    // ---- One-time: sample fused weights into gate-interleaved layout ----
    for (int i = tid; i < KTOT * Gg; i += NTH) {
        int k = i / Gg, col = i - k * Gg;          // col = g*50 + jj
        float mu, rho, ep;
        if (k < INP) { mu = wi_mu[i]; rho = wi_rho[i]; ep = eps_wi[i]; }
        else { int i2 = i - INP * Gg; mu = wh_mu[i2]; rho = wh_rho[i2]; ep = eps_wh[i2]; }
        int g = col / Hh, jj = col - g * Hh;
        w_s[k * Gg + jj * 4 + g] = fmaf(log1pf(__expf(rho)), ep, mu);
    }
    for (int i = tid; i < Hh * ROWS; i += NTH) xhA[INP * ROWS + i] = 0.0f;
    {
        const int r = tid / INP, k = tid % INP;
        if (tid < INP * ROWS) {
            float v = 0.0f;
            if (row0 + r < Bsz) v = x[(size_t)(row0 + r) * (Tt * INP) + k];
            xhA[k * ROWS + r] = v;
        }
    }

    // ---- Task map: lane-adjacent pair per (jj, 4-row) tile ----
    const bool act  = (tid < 700);
    const int  tile = act ? (tid >> 1) : 349;
    const int  kh   = tid & 1;
    const int  jj   = tile % 50;         // h-column
    const int  rr0  = (tile / 50) * 4;   // rows rr0..rr0+3
    const int  kbeg = kh ? KSPL : 0;
    const int  kend = kh ? KTOT : KSPL;

    // bias gate-pairs (kh==0 lanes only; flows through the pair reduction)
    u64 biasIF = 0ull, biasGO = 0ull;
    if (kh == 0) {
        float bi = fmaf(log1pf(__expf(b_rho[jj])),           eps_b[jj],           b_mu[jj]);
        float bf = fmaf(log1pf(__expf(b_rho[Hh + jj])),      eps_b[Hh + jj],      b_mu[Hh + jj]);
        float bg = fmaf(log1pf(__expf(b_rho[2 * Hh + jj])),  eps_b[2 * Hh + jj],  b_mu[2 * Hh + jj]);
        float bo = fmaf(log1pf(__expf(b_rho[3 * Hh + jj])),  eps_b[3 * Hh + jj],  b_mu[3 * Hh + jj]);
        biasIF = pack2(bi, bf);
        biasGO = pack2(bg, bo);
    }

    // x prefetch map (1 elem/thread)
    const int  pr = tid / INP, pk = tid % INP;
    const bool pf_ok = (tid < INP * ROWS) && (row0 + pr < Bsz);
    const size_t pf_base = pf_ok ? ((size_t)(row0 + pr) * (Tt * INP) + pk) : 0;

    // cell state in registers: this lane owns rows rr0+2*kh, rr0+2*kh+1
    float c0 = 0.0f, c1 = 0.0f;

    const float* wp = w_s + jj * 4;
    __syncthreads();

    for (int t = 0; t < Tt; ++t) {
        const float* cur = (t & 1) ? xhB : xhA;
        float*       nxt = (t & 1) ? xhA : xhB;

        float pf = 0.0f;
        if (pf_ok && t + 1 < Tt) pf = x[pf_base + (size_t)(t + 1) * INP];

        // ---- Gate GEMM: accumulators (gate-pair, row): aIF[r]=(i,f), aGO[r]=(g,o) ----
        u64 aIF0 = biasIF, aIF1 = biasIF, aIF2 = biasIF, aIF3 = biasIF;
        u64 aGO0 = biasGO, aGO1 = biasGO, aGO2 = biasGO, aGO3 = biasGO;

        const float* vrow = cur + rr0;
        #pragma unroll 4
        for (int k = kbeg; k < kend; ++k) {
            ulonglong2 wv = *(const ulonglong2*)(wp + k * Gg);   // .x=(w_i,w_f) .y=(w_g,w_o)
            float4 hv = *(const float4*)(vrow + k * ROWS);       // rows rr0..rr0+3
            u64 h0 = pack2(hv.x, hv.x);
            u64 h1 = pack2(hv.y, hv.y);
            u64 h2 = pack2(hv.z, hv.z);
            u64 h3 = pack2(hv.w, hv.w);
            aIF0 = fma2(wv.x, h0, aIF0);  aGO0 = fma2(wv.y, h0, aGO0);
            aIF1 = fma2(wv.x, h1, aIF1);  aGO1 = fma2(wv.y, h1, aGO1);
            aIF2 = fma2(wv.x, h2, aIF2);  aGO2 = fma2(wv.y, h2, aGO2);
            aIF3 = fma2(wv.x, h3, aIF3);  aGO3 = fma2(wv.y, h3, aGO3);
        }

        // ---- Pair reduction: send partner's rows, keep own (rows 2kh, 2kh+1) ----
        u64 pIF0 = shfl_pair64(kh ? aIF0 : aIF2);
        u64 pIF1 = shfl_pair64(kh ? aIF1 : aIF3);
        u64 pGO0 = shfl_pair64(kh ? aGO0 : aGO2);
        u64 pGO1 = shfl_pair64(kh ? aGO1 : aGO3);
        u64 fIF0 = add2(kh ? aIF2 : aIF0, pIF0);
        u64 fIF1 = add2(kh ? aIF3 : aIF1, pIF1);
        u64 fGO0 = add2(kh ? aGO2 : aGO0, pGO0);
        u64 fGO1 = add2(kh ? aGO3 : aGO1, pGO1);

        // ---- In-register epilogue on this lane's 2 rows ----
        {
            float gi0, gf0, gi1, gf1, gg0, go0, gg1, go1;
            unpack2(fIF0, gi0, gf0);
            unpack2(fIF1, gi1, gf1);
            unpack2(fGO0, gg0, go0);
            unpack2(fGO1, gg1, go1);
            float cn0 = fmaf(sigf(gf0), c0, sigf(gi0) * tanh_fast(gg0));
            float cn1 = fmaf(sigf(gf1), c1, sigf(gi1) * tanh_fast(gg1));
            c0 = cn0; c1 = cn1;
            float h0 = sigf(go0) * tanh_fast(cn0);
            float h1 = sigf(go1) * tanh_fast(cn1);
            if (act)
                *(float2*)(nxt + (INP + jj) * ROWS + rr0 + 2 * kh) = make_float2(h0, h1);
        }

        // commit prefetched x(t+1)
        if (pf_ok && t + 1 < Tt) nxt[pk * ROWS + pr] = pf;

        __syncthreads();   // one barrier per step
    }

    // ---- Head: t=511 (odd) wrote nxt = xhA ----
    if (tid < ROWS && row0 + tid < Bsz) {
        float s = lin_b[0];
        #pragma unroll
        for (int m = 0; m < Hh; m++)
            s = fmaf(xhA[(INP + m) * ROWS + tid], lin_w[m], s);
        out[row0 + tid] = s;
    }
}

extern "C" void kernel_launch(void* const* d_in, const int* in_sizes, int n_in,
                              void* d_out, int out_size)
{
    const size_t smem_bytes =
        (size_t)(KTOT * Gg + 2 * KTOT * ROWS) * sizeof(float);   // 76800 B
    cudaFuncSetAttribute(bayes_lstm_kernel,
                         cudaFuncAttributeMaxDynamicSharedMemorySize,
                         (int)smem_bytes);
    bayes_lstm_kernel<<<GRID, NTH, smem_bytes>>>(
        (const float*)d_in[0],  (const float*)d_in[1],  (const float*)d_in[2],
        (const float*)d_in[3],  (const float*)d_in[4],  (const float*)d_in[5],
        (const float*)d_in[6],  (const float*)d_in[7],  (const float*)d_in[8],
        (const float*)d_in[9],  (const float*)d_in[10], (const float*)d_in[11],
        (float*)d_out);
}

// round 9
// speedup vs baseline: 1.2815x; 1.2815x over previous
#include <cuda_runtime.h>
#include <math.h>

#define Bsz  4096
#define Tt   512
#define INP  25
#define Hh   50
#define Gg   200
#define KTOT 76          // padded (row 75 = zero weights)
#define KSPL 38          // kh0: k in [0,38), kh1: [38,76)
#define ROWS 28
#define NTH  704         // 22 warps
#define GRID 147

typedef unsigned long long u64;

__device__ __forceinline__ float tanhap(float v) {
    float r; asm("tanh.approx.f32 %0, %1;" : "=f"(r) : "f"(v)); return r;
}
__device__ __forceinline__ float sigf(float v) {
    return fmaf(0.5f, tanhap(0.5f * v), 0.5f);
}
__device__ __forceinline__ u64 pack2(float lo, float hi) {
    u64 d; asm("mov.b64 %0, {%1, %2};" : "=l"(d) : "f"(lo), "f"(hi)); return d;
}
__device__ __forceinline__ void unpack2(u64 d, float& lo, float& hi) {
    asm("mov.b64 {%0, %1}, %2;" : "=f"(lo), "=f"(hi) : "l"(d));
}
__device__ __forceinline__ u64 fma2(u64 a, u64 b, u64 c) {
    u64 d; asm("fma.rn.f32x2 %0, %1, %2, %3;" : "=l"(d) : "l"(a), "l"(b), "l"(c)); return d;
}
__device__ __forceinline__ u64 add2(u64 a, u64 b) {
    u64 d; asm("add.rn.f32x2 %0, %1, %2;" : "=l"(d) : "l"(a), "l"(b)); return d;
}
__device__ __forceinline__ u64 shfl_xor64(u64 v, int m) {
    float lo, hi; unpack2(v, lo, hi);
    lo = __shfl_xor_sync(0xffffffffu, lo, m);
    hi = __shfl_xor_sync(0xffffffffu, hi, m);
    return pack2(lo, hi);
}

__global__ void __launch_bounds__(NTH, 1)
bayes_lstm_kernel(const float* __restrict__ x,
                  const float* __restrict__ wi_mu, const float* __restrict__ wi_rho,
                  const float* __restrict__ wh_mu, const float* __restrict__ wh_rho,
                  const float* __restrict__ b_mu,  const float* __restrict__ b_rho,
                  const float* __restrict__ lin_w, const float* __restrict__ lin_b,
                  const float* __restrict__ eps_wi, const float* __restrict__ eps_wh,
                  const float* __restrict__ eps_b,
                  float* __restrict__ out)
{
    extern __shared__ float sm[];
    float* w_s = sm;                     // [76][Gg] gate-interleaved: w_s[k][jj*4+g] = W[k][g*50+jj]
    float* xhA = w_s + KTOT * Gg;        // [76][ROWS] buf 0 (x rows 0..24, h rows 25..74, row 75 zero)
    float* xhB = xhA + KTOT * ROWS;      // [76][ROWS] buf 1

    const int tid  = threadIdx.x;
    const long row0 = (long)blockIdx.x * ROWS;

    // ---- One-time: sample fused weights into gate-interleaved layout ----
    for (int i = tid; i < 75 * Gg; i += NTH) {
        int k = i / Gg, col = i - k * Gg;          // col = g*50 + jj
        float mu, rho, ep;
        if (k < INP) { mu = wi_mu[i]; rho = wi_rho[i]; ep = eps_wi[i]; }
        else { int i2 = i - INP * Gg; mu = wh_mu[i2]; rho = wh_rho[i2]; ep = eps_wh[i2]; }
        int g = col / Hh, jj = col - g * Hh;
        w_s[k * Gg + jj * 4 + g] = fmaf(log1pf(__expf(rho)), ep, mu);
    }
    // zero pad row 75 of weights, h rows of buf 0, and row 75 of both xh buffers
    for (int i = tid; i < Gg; i += NTH) w_s[75 * Gg + i] = 0.0f;
    for (int i = tid; i < Hh * ROWS; i += NTH) xhA[INP * ROWS + i] = 0.0f;
    for (int i = tid; i < ROWS; i += NTH) {
        xhA[75 * ROWS + i] = 0.0f;
        xhB[75 * ROWS + i] = 0.0f;
    }
    // x(t=0) into buf 0 (700 elems; one per thread, tid<700)
    {
        const int r = tid / INP, k = tid % INP;
        if (tid < INP * ROWS) {
            float v = 0.0f;
            if (row0 + r < Bsz) v = x[(size_t)(row0 + r) * (Tt * INP) + k];
            xhA[k * ROWS + r] = v;
        }
    }

    // ---- Task map: pair of lane-adjacent threads per (jj, 4-row) tile ----
    const bool act  = (tid < 700);
    const int  tile = act ? (tid >> 1) : 349;
    const int  kh   = tid & 1;
    const int  jj   = tile % 50;         // h-column
    const int  rr0  = (tile / 50) * 4;   // rows rr0..rr0+3
    const int  kbeg = kh ? KSPL : 0;

    // bias (kh==0 lanes only; flows through the bidirectional pair reduction)
    u64 bias2[4];
    #pragma unroll
    for (int g = 0; g < 4; g++) {
        float b = 0.0f;
        if (kh == 0) {
            int j = g * Hh + jj;
            b = fmaf(log1pf(__expf(b_rho[j])), eps_b[j], b_mu[j]);
        }
        bias2[g] = pack2(b, b);
    }

    // x prefetch map (1 elem/thread)
    const int  pr = tid / INP, pk = tid % INP;
    const bool pf_ok = (tid < INP * ROWS) && (row0 + pr < Bsz);
    const size_t pf_base = pf_ok ? ((size_t)(row0 + pr) * (Tt * INP) + pk) : 0;

    // cell state in registers: this lane owns rows rr0+2*kh, rr0+2*kh+1
    float c0 = 0.0f, c1 = 0.0f;

    const float* wp = w_s + jj * 4;
    __syncthreads();

    for (int t = 0; t < Tt; ++t) {
        const float* cur = (t & 1) ? xhB : xhA;
        float*       nxt = (t & 1) ? xhA : xhB;

        float pf = 0.0f;
        if (pf_ok && t + 1 < Tt) pf = x[pf_base + (size_t)(t + 1) * INP];

        // ---- Gate GEMM: a[g][vp], vp=0 -> rows (rr0,rr0+1), vp=1 -> (rr0+2,rr0+3) ----
        u64 a0[2], a1[2], a2[2], a3[2];
        a0[0] = bias2[0]; a0[1] = bias2[0];
        a1[0] = bias2[1]; a1[1] = bias2[1];
        a2[0] = bias2[2]; a2[1] = bias2[2];
        a3[0] = bias2[3]; a3[1] = bias2[3];

        const float* vrow = cur + rr0;
        const float* wk = wp + kbeg * Gg;
        const float* vk = vrow + kbeg * ROWS;
        #pragma unroll 2
        for (int i = 0; i < KSPL; ++i) {
            float4 w4 = *(const float4*)(wk);      // (i,f,g,o) of column jj
            float4 hv = *(const float4*)(vk);      // rows rr0..rr0+3
            wk += Gg; vk += ROWS;
            u64 h01 = pack2(hv.x, hv.y);
            u64 h23 = pack2(hv.z, hv.w);
            u64 wd;
            wd = pack2(w4.x, w4.x); a0[0] = fma2(wd, h01, a0[0]); a0[1] = fma2(wd, h23, a0[1]);
            wd = pack2(w4.y, w4.y); a1[0] = fma2(wd, h01, a1[0]); a1[1] = fma2(wd, h23, a1[1]);
            wd = pack2(w4.z, w4.z); a2[0] = fma2(wd, h01, a2[0]); a2[1] = fma2(wd, h23, a2[1]);
            wd = pack2(w4.w, w4.w); a3[0] = fma2(wd, h01, a3[0]); a3[1] = fma2(wd, h23, a3[1]);
        }

        // ---- Bidirectional pair reduction: both lanes get full sums ----
        #pragma unroll
        for (int vp = 0; vp < 2; vp++) {
            a0[vp] = add2(a0[vp], shfl_xor64(a0[vp], 1));
            a1[vp] = add2(a1[vp], shfl_xor64(a1[vp], 1));
            a2[vp] = add2(a2[vp], shfl_xor64(a2[vp], 1));
            a3[vp] = add2(a3[vp], shfl_xor64(a3[vp], 1));
        }

        // ---- In-register epilogue: this lane's 2 rows (vp = kh) ----
        {
            float gi0, gi1, gf0, gf1, gg0, gg1, go0, go1;
            unpack2(a0[kh], gi0, gi1);
            unpack2(a1[kh], gf0, gf1);
            unpack2(a2[kh], gg0, gg1);
            unpack2(a3[kh], go0, go1);
            float cn0 = fmaf(sigf(gf0), c0, sigf(gi0) * tanhap(gg0));
            float cn1 = fmaf(sigf(gf1), c1, sigf(gi1) * tanhap(gg1));
            c0 = cn0; c1 = cn1;
            float h0 = sigf(go0) * tanhap(cn0);
            float h1 = sigf(go1) * tanhap(cn1);
            if (act)
                *(float2*)(nxt + (INP + jj) * ROWS + rr0 + 2 * kh) = make_float2(h0, h1);
        }

        // commit prefetched x(t+1)
        if (pf_ok && t + 1 < Tt) nxt[pk * ROWS + pr] = pf;

        __syncthreads();   // one barrier per step
    }

    // ---- Head: t=511 (odd) wrote nxt = xhA ----
    if (tid < ROWS && row0 + tid < Bsz) {
        float s = lin_b[0];
        #pragma unroll
        for (int m = 0; m < Hh; m++)
            s = fmaf(xhA[(INP + m) * ROWS + tid], lin_w[m], s);
        out[row0 + tid] = s;
    }
}

extern "C" void kernel_launch(void* const* d_in, const int* in_sizes, int n_in,
                              void* d_out, int out_size)
{
    const size_t smem_bytes =
        (size_t)(KTOT * Gg + 2 * KTOT * ROWS) * sizeof(float);   // 77824 B
    cudaFuncSetAttribute(bayes_lstm_kernel,
                         cudaFuncAttributeMaxDynamicSharedMemorySize,
                         (int)smem_bytes);
    bayes_lstm_kernel<<<GRID, NTH, smem_bytes>>>(
        (const float*)d_in[0],  (const float*)d_in[1],  (const float*)d_in[2],
        (const float*)d_in[3],  (const float*)d_in[4],  (const float*)d_in[5],
        (const float*)d_in[6],  (const float*)d_in[7],  (const float*)d_in[8],
        (const float*)d_in[9],  (const float*)d_in[10], (const float*)d_in[11],
        (float*)d_out);
}